// round 3
// baseline (speedup 1.0000x reference)
#include <cuda_runtime.h>
#include <math.h>

// Problem-shape constants (fixed by the dataset)
#define NN 100000
#define EE 1600000
#define VV 256
#define HH 128

// ---------------- scratch (static device globals: allocation-free) ----------
// float4 arrays to guarantee 16B alignment for vector accesses.
__device__ float4 g_bufA4[(size_t)NN * HH / 4];   // h_pre (x@W1), later h2_pre
__device__ float4 g_bufB4[(size_t)NN * HH / 4];   // scatter accumulator -> h
__device__ float4 g_res4 [(size_t)NN * HH / 4];   // residual x@Wres
__device__ float  g_norm[EE];
__device__ float  g_dis [NN];
__device__ float  g_deg [NN];
__device__ float  g_s   [NN];                     // h2 @ W3 scalar per node

#define SEL_A 0
#define SEL_B 1
#define SEL_R 2
__device__ __forceinline__ float* pick(int sel) {
    return sel == SEL_A ? (float*)g_bufA4
         : (sel == SEL_B ? (float*)g_bufB4 : (float*)g_res4);
}

// ---------------- small elementwise kernels ---------------------------------
__global__ void k_init_deg(int n) {
    int i = blockIdx.x * blockDim.x + threadIdx.x;
    if (i < n) g_deg[i] = 1.0f;   // self-loop weight
}

__global__ void k_accum_deg(const int* __restrict__ ei,
                            const float* __restrict__ ew, int E) {
    int e = blockIdx.x * blockDim.x + threadIdx.x;
    if (e < E) atomicAdd(&g_deg[ei[E + e]], ew[e]);
}

__global__ void k_dis(int n) {
    int i = blockIdx.x * blockDim.x + threadIdx.x;
    if (i < n) g_dis[i] = rsqrtf(g_deg[i]);     // deg >= 1 always
}

__global__ void k_norm(const int* __restrict__ ei,
                       const float* __restrict__ ew, int E) {
    int e = blockIdx.x * blockDim.x + threadIdx.x;
    if (e < E) {
        int r = ei[e];
        int c = ei[E + e];
        g_norm[e] = g_dis[r] * ew[e] * g_dis[c];
    }
}

__global__ void k_fill0(int sel, int n) {
    int i = blockIdx.x * blockDim.x + threadIdx.x;
    if (i < n) pick(sel)[i] = 0.0f;
}

// ---------------- SGEMM: C[M,128] = A[M,K] @ B[K,128] -----------------------
// BM=128, BN=128, BK=8, 256 threads, 8x8 per-thread microtile.
__global__ __launch_bounds__(256)
void sgemm_n128(const float* __restrict__ A_ext, int selA,
                const float* __restrict__ B, int selC, int M, int K) {
    const float* A = (selA < 0) ? A_ext : pick(selA);
    float* C = pick(selC);

    __shared__ float As[8][128];   // transposed: As[k][row]
    __shared__ float Bs[8][128];

    int tid  = threadIdx.x;
    int row0 = blockIdx.x * 128;
    int tx = tid % 16, ty = tid / 16;

    int aR = tid >> 1;
    int aC = (tid & 1) * 4;
    int bK = tid >> 5;
    int bC = (tid & 31) * 4;

    float acc[8][8];
    #pragma unroll
    for (int i = 0; i < 8; i++)
        #pragma unroll
        for (int j = 0; j < 8; j++) acc[i][j] = 0.0f;

    for (int k0 = 0; k0 < K; k0 += 8) {
        int gr = row0 + aR;
        float4 av = make_float4(0.f, 0.f, 0.f, 0.f);
        if (gr < M) av = *(const float4*)(A + (size_t)gr * K + k0 + aC);
        As[aC + 0][aR] = av.x;
        As[aC + 1][aR] = av.y;
        As[aC + 2][aR] = av.z;
        As[aC + 3][aR] = av.w;

        float4 bv = *(const float4*)(B + (size_t)(k0 + bK) * 128 + bC);
        *(float4*)&Bs[bK][bC] = bv;
        __syncthreads();

        #pragma unroll
        for (int kk = 0; kk < 8; kk++) {
            float a[8], b[8];
            #pragma unroll
            for (int i = 0; i < 8; i++) a[i] = As[kk][ty * 8 + i];
            #pragma unroll
            for (int j = 0; j < 8; j++) b[j] = Bs[kk][tx * 8 + j];
            #pragma unroll
            for (int i = 0; i < 8; i++)
                #pragma unroll
                for (int j = 0; j < 8; j++)
                    acc[i][j] += a[i] * b[j];
        }
        __syncthreads();
    }

    #pragma unroll
    for (int i = 0; i < 8; i++) {
        int gr = row0 + ty * 8 + i;
        if (gr < M) {
            float4* cp = (float4*)(C + (size_t)gr * 128 + tx * 8);
            cp[0] = make_float4(acc[i][0], acc[i][1], acc[i][2], acc[i][3]);
            cp[1] = make_float4(acc[i][4], acc[i][5], acc[i][6], acc[i][7]);
        }
    }
}

// ---------------- edge scatter, 128-wide (1 warp per edge) ------------------
__global__ void k_scatter128(int selH, int selOut,
                             const int* __restrict__ ei, int E) {
    const float* h = pick(selH);
    float* out = pick(selOut);
    long long t = (long long)blockIdx.x * blockDim.x + threadIdx.x;
    int e = (int)(t >> 5);
    if (e >= E) return;
    int lane = (int)(t & 31);
    int r = ei[e];
    int c = ei[E + e];
    float nm = g_norm[e];
    float4 hv = *(const float4*)(h + (size_t)r * 128 + lane * 4);
    float* dst = out + (size_t)c * 128 + lane * 4;
    atomicAdd(dst + 0, hv.x * nm);
    atomicAdd(dst + 1, hv.y * nm);
    atomicAdd(dst + 2, hv.z * nm);
    atomicAdd(dst + 3, hv.w * nm);
}

// ---------------- fused epilogue: +selfloop +bias (+res), BN, ReLU ----------
__global__ void k_epilogue(int selIO, int selHpre,
                           const float* __restrict__ bvec,
                           const float* __restrict__ g, const float* __restrict__ be,
                           const float* __restrict__ m, const float* __restrict__ v,
                           int selRes,  // -1 = none
                           int total) {
    float* io = pick(selIO);
    const float* hpre = pick(selHpre);
    int idx = blockIdx.x * blockDim.x + threadIdx.x;
    if (idx >= total) return;
    int j   = idx & 127;
    int row = idx >> 7;
    float d  = g_dis[row];
    float hs = io[idx] + hpre[idx] * d * d + bvec[j];
    if (selRes >= 0) hs += pick(selRes)[idx];
    float sc = g[j] * rsqrtf(v[j] + 1e-5f);
    float y  = (hs - m[j]) * sc + be[j];
    io[idx] = fmaxf(y, 0.0f);
}

// ---------------- GEMV: s[i] = h[i,:] . w3 (1 warp per row) -----------------
__global__ void k_gemv(int selH, const float* __restrict__ w3, int n) {
    const float* h = pick(selH);
    int warp = (blockIdx.x * blockDim.x + threadIdx.x) >> 5;
    int lane = threadIdx.x & 31;
    if (warp >= n) return;
    float4 hv = ((const float4*)(h + (size_t)warp * 128))[lane];
    float4 wv = ((const float4*)w3)[lane];
    float sum = hv.x * wv.x + hv.y * wv.y + hv.z * wv.z + hv.w * wv.w;
    #pragma unroll
    for (int o = 16; o > 0; o >>= 1) sum += __shfl_down_sync(0xffffffffu, sum, o);
    if (lane == 0) g_s[warp] = sum;
}

__global__ void k_out_init(const float* __restrict__ b3, float* __restrict__ out, int n) {
    int i = blockIdx.x * blockDim.x + threadIdx.x;
    if (i < n) {
        float d = g_dis[i];
        out[i] = b3[0] + g_s[i] * d * d;   // bias + self loop
    }
}

__global__ void k_scatter1(const int* __restrict__ ei,
                           float* __restrict__ out, int E) {
    int e = blockIdx.x * blockDim.x + threadIdx.x;
    if (e < E) atomicAdd(&out[ei[E + e]], g_s[ei[e]] * g_norm[e]);
}

// ---------------- launch ----------------------------------------------------
extern "C" void kernel_launch(void* const* d_in, const int* in_sizes, int n_in,
                              void* d_out, int out_size) {
    const float* x    = (const float*)d_in[0];
    const int*   ei   = (const int*)d_in[1];     // int32 (JAX x64 disabled)
    const float* ew   = (const float*)d_in[2];
    const float* W1   = (const float*)d_in[3];
    const float* b1   = (const float*)d_in[4];
    const float* W2   = (const float*)d_in[5];
    const float* b2   = (const float*)d_in[6];
    const float* W3   = (const float*)d_in[7];
    const float* b3   = (const float*)d_in[8];
    const float* Wres = (const float*)d_in[9];
    const float* g1   = (const float*)d_in[10];
    const float* be1  = (const float*)d_in[11];
    const float* m1   = (const float*)d_in[12];
    const float* v1   = (const float*)d_in[13];
    const float* g2   = (const float*)d_in[14];
    const float* be2  = (const float*)d_in[15];
    const float* m2   = (const float*)d_in[16];
    const float* v2   = (const float*)d_in[17];
    float* out = (float*)d_out;
    (void)n_in;

    const int N  = out_size;          // 100000
    const int E  = in_sizes[1] / 2;   // 1600000
    const int K1 = in_sizes[0] / N;   // 256

    const int T = 256;
    int nb_N   = (N + T - 1) / T;
    int nb_E   = (E + T - 1) / T;
    int total  = N * 128;
    int nb_tot = (total + T - 1) / T;
    long long wthreads = (long long)E * 32;
    int nb_Ew  = (int)((wthreads + T - 1) / T);
    int nb_M   = (N + 127) / 128;
    int nb_gemv = (N * 32 + T - 1) / T;

    // --- normalization precompute ---
    k_init_deg<<<nb_N, T>>>(N);
    k_accum_deg<<<nb_E, T>>>(ei, ew, E);
    k_dis<<<nb_N, T>>>(N);
    k_norm<<<nb_E, T>>>(ei, ew, E);

    // --- layer 1: h1_pre = x@W1, res = x@Wres ---
    sgemm_n128<<<nb_M, T>>>(x, -1, W1,   SEL_A, N, K1);
    sgemm_n128<<<nb_M, T>>>(x, -1, Wres, SEL_R, N, K1);

    // --- propagate 1 + BN/ReLU epilogue (self loop fused) ---
    k_fill0<<<nb_tot, T>>>(SEL_B, total);
    k_scatter128<<<nb_Ew, T>>>(SEL_A, SEL_B, ei, E);
    k_epilogue<<<nb_tot, T>>>(SEL_B, SEL_A, b1, g1, be1, m1, v1, -1, total);

    // --- layer 2: h2_pre = h1@W2 ---
    sgemm_n128<<<nb_M, T>>>(nullptr, SEL_B, W2, SEL_A, N, 128);

    // --- propagate 2 + residual + BN/ReLU ---
    k_fill0<<<nb_tot, T>>>(SEL_B, total);   // bufB (h1) dead after GEMM2: stream-ordered
    k_scatter128<<<nb_Ew, T>>>(SEL_A, SEL_B, ei, E);
    k_epilogue<<<nb_tot, T>>>(SEL_B, SEL_A, b2, g2, be2, m2, v2, SEL_R, total);

    // --- layer 3: scalar conv ---
    k_gemv<<<nb_gemv, T>>>(SEL_B, W3, N);
    k_out_init<<<nb_N, T>>>(b3, out, N);
    k_scatter1<<<nb_E, T>>>(ei, out, E);
}

// round 5
// speedup vs baseline: 1.3571x; 1.3571x over previous
#include <cuda_runtime.h>
#include <mma.h>
#include <math.h>

using namespace nvcuda;

// Problem-shape constants (fixed by the dataset)
#define NN 100000
#define EE 1600000
#define HH 128
#define NPAD (NN + 128)   // pad so GEMM tiles can store unguarded

// ---------------- scratch (static device globals: allocation-free) ----------
__device__ float4 g_bufA4[(size_t)NPAD * HH / 4];
__device__ float4 g_bufB4[(size_t)NPAD * HH / 4];
__device__ float4 g_res4 [(size_t)NPAD * HH / 4];
__device__ float  g_norm[EE];
__device__ float  g_dis [NN];
__device__ float  g_deg [NN];

#define SEL_A 0
#define SEL_B 1
#define SEL_R 2
__device__ __forceinline__ float* pick(int sel) {
    return sel == SEL_A ? (float*)g_bufA4
         : (sel == SEL_B ? (float*)g_bufB4 : (float*)g_res4);
}

// ---------------- small elementwise kernels ---------------------------------
__global__ void k_init_deg(int n) {
    int i = blockIdx.x * blockDim.x + threadIdx.x;
    if (i < n) g_deg[i] = 1.0f;   // self-loop weight
}

__global__ void k_accum_deg(const int* __restrict__ ei,
                            const float* __restrict__ ew, int E) {
    int e = blockIdx.x * blockDim.x + threadIdx.x;
    if (e < E) atomicAdd(&g_deg[ei[E + e]], ew[e]);
}

__global__ void k_dis(int n) {
    int i = blockIdx.x * blockDim.x + threadIdx.x;
    if (i < n) g_dis[i] = rsqrtf(g_deg[i]);
}

__global__ void k_norm(const int* __restrict__ ei,
                       const float* __restrict__ ew, int E) {
    int e = blockIdx.x * blockDim.x + threadIdx.x;
    if (e < E) g_norm[e] = g_dis[ei[e]] * ew[e] * g_dis[ei[E + e]];
}

__global__ void k_fill0(int sel, int n4) {   // n4 = count of float4
    int i = blockIdx.x * blockDim.x + threadIdx.x;
    if (i < n4) ((float4*)pick(sel))[i] = make_float4(0.f, 0.f, 0.f, 0.f);
}

// ---------------- tf32 tensor-core GEMM: C[M,128] = A[M,K] @ B[K,128] --------
// Block tile 128x128, 256 threads (8 warps in 2x4), warp tile 64x32.
// 3xTF32 split (hi/lo) for ~fp32 accuracy. Stores unguarded (C is padded scratch).
__global__ __launch_bounds__(256)
void gemm_tf32(const float* __restrict__ A_ext, int selA,
               const float* __restrict__ B, int selC, int M, int K) {
    const float* A = (selA < 0) ? A_ext : pick(selA);
    float* C = pick(selC);

    __shared__ float As[128][40];   // 128x32 tile, pad->40 (16B-aligned rows)
    __shared__ float Bs[32][136];   // 32x128 tile, pad->136

    int tid = threadIdx.x;
    int wid = tid >> 5;
    int warpM = wid >> 2;     // 0..1 -> 64 rows each
    int warpN = wid & 3;      // 0..3 -> 32 cols each
    int row0 = blockIdx.x * 128;

    wmma::fragment<wmma::accumulator, 16, 16, 8, float> acc[4][2];
    #pragma unroll
    for (int i = 0; i < 4; i++)
        #pragma unroll
        for (int j = 0; j < 2; j++) wmma::fill_fragment(acc[i][j], 0.0f);

    int ar = tid >> 3;            // 0..31
    int ac = (tid & 7) * 4;       // 0,4,...,28
    int br = tid >> 6;            // 0..3
    int bc = (tid & 63) * 2;      // 0..126 step 2  (float2 per thread x 8 rows)

    for (int k0 = 0; k0 < K; k0 += 32) {
        // A tile: 128 rows x 32 cols
        #pragma unroll
        for (int p = 0; p < 4; p++) {
            int r = ar + p * 32;
            int gr = row0 + r;
            float4 v = make_float4(0.f, 0.f, 0.f, 0.f);
            if (gr < M) v = *(const float4*)(A + (size_t)gr * K + k0 + ac);
            *(float4*)&As[r][ac] = v;
        }
        // B tile: 32 rows x 128 cols (float2 per thread, 4 rows/pass, 8 passes)
        #pragma unroll
        for (int p = 0; p < 8; p++) {
            int r = br + p * 4;
            float2 v = *(const float2*)(B + (size_t)(k0 + r) * 128 + bc);
            *(float2*)&Bs[r][bc] = v;
        }
        __syncthreads();

        #pragma unroll
        for (int kk = 0; kk < 32; kk += 8) {
            wmma::fragment<wmma::matrix_a, 16, 16, 8, wmma::precision::tf32, wmma::row_major> ah[4], al[4];
            wmma::fragment<wmma::matrix_b, 16, 16, 8, wmma::precision::tf32, wmma::row_major> bh[2], bl[2];
            #pragma unroll
            for (int i = 0; i < 4; i++) {
                wmma::load_matrix_sync(ah[i], &As[warpM * 64 + i * 16][kk], 40);
                #pragma unroll
                for (int t = 0; t < ah[i].num_elements; t++) {
                    float x = ah[i].x[t];
                    float h = wmma::__float_to_tf32(x);
                    ah[i].x[t] = h;
                    al[i].x[t] = wmma::__float_to_tf32(x - h);
                }
            }
            #pragma unroll
            for (int j = 0; j < 2; j++) {
                wmma::load_matrix_sync(bh[j], &Bs[kk][warpN * 32 + j * 16], 136);
                #pragma unroll
                for (int t = 0; t < bh[j].num_elements; t++) {
                    float x = bh[j].x[t];
                    float h = wmma::__float_to_tf32(x);
                    bh[j].x[t] = h;
                    bl[j].x[t] = wmma::__float_to_tf32(x - h);
                }
            }
            #pragma unroll
            for (int i = 0; i < 4; i++)
                #pragma unroll
                for (int j = 0; j < 2; j++) {
                    wmma::mma_sync(acc[i][j], al[i], bh[j], acc[i][j]);
                    wmma::mma_sync(acc[i][j], ah[i], bl[j], acc[i][j]);
                    wmma::mma_sync(acc[i][j], ah[i], bh[j], acc[i][j]);
                }
        }
        __syncthreads();
    }

    #pragma unroll
    for (int i = 0; i < 4; i++)
        #pragma unroll
        for (int j = 0; j < 2; j++) {
            float* cp = C + (size_t)(row0 + warpM * 64 + i * 16) * 128 + warpN * 32 + j * 16;
            wmma::store_matrix_sync(cp, acc[i][j], 128, wmma::mem_row_major);
        }
}

// ---------------- edge scatter, 128-wide (1 warp per edge, v4 red) ----------
__global__ void k_scatter128(int selH, int selOut,
                             const int* __restrict__ ei, int E) {
    const float* h = pick(selH);
    float* out = pick(selOut);
    long long t = (long long)blockIdx.x * blockDim.x + threadIdx.x;
    int e = (int)(t >> 5);
    if (e >= E) return;
    int lane = (int)(t & 31);
    int r = ei[e];
    int c = ei[E + e];
    float nm = g_norm[e];
    float4 hv = *(const float4*)(h + (size_t)r * 128 + lane * 4);
    float* dst = out + (size_t)c * 128 + lane * 4;
    asm volatile("red.global.add.v4.f32 [%0], {%1, %2, %3, %4};"
                 :: "l"(dst), "f"(hv.x * nm), "f"(hv.y * nm),
                    "f"(hv.z * nm), "f"(hv.w * nm)
                 : "memory");
}

// ---------------- fused epilogue: +selfloop +bias (+res), BN, ReLU ----------
// One float4 per thread: total threads = N*32.
__global__ void k_epilogue(int selIO, int selHpre,
                           const float* __restrict__ bvec,
                           const float* __restrict__ g, const float* __restrict__ be,
                           const float* __restrict__ m, const float* __restrict__ v,
                           int selRes, int n4) {
    float4* io = (float4*)pick(selIO);
    const float4* hpre = (const float4*)pick(selHpre);
    int idx = blockIdx.x * blockDim.x + threadIdx.x;
    if (idx >= n4) return;
    int j4  = (idx & 31) * 4;
    int row = idx >> 5;
    float d2 = g_dis[row]; d2 *= d2;

    float4 a = io[idx];
    float4 p = hpre[idx];
    float4 bv = *(const float4*)(bvec + j4);
    a.x += p.x * d2 + bv.x; a.y += p.y * d2 + bv.y;
    a.z += p.z * d2 + bv.z; a.w += p.w * d2 + bv.w;
    if (selRes >= 0) {
        float4 rr = ((const float4*)pick(selRes))[idx];
        a.x += rr.x; a.y += rr.y; a.z += rr.z; a.w += rr.w;
    }
    float4 gv = *(const float4*)(g + j4);
    float4 vv = *(const float4*)(v + j4);
    float4 mv = *(const float4*)(m + j4);
    float4 bb = *(const float4*)(be + j4);
    float4 o;
    o.x = fmaxf((a.x - mv.x) * (gv.x * rsqrtf(vv.x + 1e-5f)) + bb.x, 0.f);
    o.y = fmaxf((a.y - mv.y) * (gv.y * rsqrtf(vv.y + 1e-5f)) + bb.y, 0.f);
    o.z = fmaxf((a.z - mv.z) * (gv.z * rsqrtf(vv.z + 1e-5f)) + bb.z, 0.f);
    o.w = fmaxf((a.w - mv.w) * (gv.w * rsqrtf(vv.w + 1e-5f)) + bb.w, 0.f);
    io[idx] = o;
}

// ---------------- fused GEMV + self-loop + bias: out[i] = b3 + (h.w3)*d^2 ---
__global__ void k_gemv_out(int selH, const float* __restrict__ w3,
                           const float* __restrict__ b3,
                           float* __restrict__ out, int n) {
    const float* h = pick(selH);
    int warp = (blockIdx.x * blockDim.x + threadIdx.x) >> 5;
    int lane = threadIdx.x & 31;
    if (warp >= n) return;
    float4 hv = ((const float4*)(h + (size_t)warp * 128))[lane];
    float4 wv = ((const float4*)w3)[lane];
    float sum = hv.x * wv.x + hv.y * wv.y + hv.z * wv.z + hv.w * wv.w;
    #pragma unroll
    for (int o = 16; o > 0; o >>= 1) sum += __shfl_down_sync(0xffffffffu, sum, o);
    if (lane == 0) {
        float d = g_dis[warp];
        out[warp] = b3[0] + sum * d * d;
    }
}

// keep the per-node scalar s around for the final scatter (recompute-free)
__global__ void k_scatter1(const int* __restrict__ ei,
                           const float* __restrict__ b3,
                           float* __restrict__ out, int selH,
                           const float* __restrict__ w3, int E) {
    // out[c] += s[r] * norm ; s[r] recovered from out? No — recompute from h.
    // One warp per edge is too heavy; instead read s from out-form is wrong.
    // This kernel is replaced below; kept unused.
}

__device__ float g_s[NN];

__global__ void k_gemv_s(int selH, const float* __restrict__ w3, int n) {
    const float* h = pick(selH);
    int warp = (blockIdx.x * blockDim.x + threadIdx.x) >> 5;
    int lane = threadIdx.x & 31;
    if (warp >= n) return;
    float4 hv = ((const float4*)(h + (size_t)warp * 128))[lane];
    float4 wv = ((const float4*)w3)[lane];
    float sum = hv.x * wv.x + hv.y * wv.y + hv.z * wv.z + hv.w * wv.w;
    #pragma unroll
    for (int o = 16; o > 0; o >>= 1) sum += __shfl_down_sync(0xffffffffu, sum, o);
    if (lane == 0) g_s[warp] = sum;
}

__global__ void k_out_init(const float* __restrict__ b3, float* __restrict__ out, int n) {
    int i = blockIdx.x * blockDim.x + threadIdx.x;
    if (i < n) {
        float d = g_dis[i];
        out[i] = b3[0] + g_s[i] * d * d;
    }
}

__global__ void k_scatter_s(const int* __restrict__ ei, float* __restrict__ out, int E) {
    int e = blockIdx.x * blockDim.x + threadIdx.x;
    if (e < E) atomicAdd(&out[ei[E + e]], g_s[ei[e]] * g_norm[e]);
}

// ---------------- launch ----------------------------------------------------
extern "C" void kernel_launch(void* const* d_in, const int* in_sizes, int n_in,
                              void* d_out, int out_size) {
    const float* x    = (const float*)d_in[0];
    const int*   ei   = (const int*)d_in[1];     // int32 (JAX x64 disabled)
    const float* ew   = (const float*)d_in[2];
    const float* W1   = (const float*)d_in[3];
    const float* b1   = (const float*)d_in[4];
    const float* W2   = (const float*)d_in[5];
    const float* b2   = (const float*)d_in[6];
    const float* W3   = (const float*)d_in[7];
    const float* b3   = (const float*)d_in[8];
    const float* Wres = (const float*)d_in[9];
    const float* g1   = (const float*)d_in[10];
    const float* be1  = (const float*)d_in[11];
    const float* m1   = (const float*)d_in[12];
    const float* v1   = (const float*)d_in[13];
    const float* g2   = (const float*)d_in[14];
    const float* be2  = (const float*)d_in[15];
    const float* m2   = (const float*)d_in[16];
    const float* v2   = (const float*)d_in[17];
    float* out = (float*)d_out;
    (void)n_in;

    const int N  = out_size;          // 100000
    const int E  = in_sizes[1] / 2;   // 1600000
    const int K1 = in_sizes[0] / N;   // 256

    const int T = 256;
    int nb_N   = (N + T - 1) / T;
    int nb_E   = (E + T - 1) / T;
    int n4     = N * 32;              // float4 count of an N x 128 buffer
    int nb_4   = (n4 + T - 1) / T;
    long long wthreads = (long long)E * 32;
    int nb_Ew  = (int)((wthreads + T - 1) / T);
    int nb_M   = (N + 127) / 128;
    int nb_warp = (N * 32 + T - 1) / T;

    // --- normalization precompute ---
    k_init_deg<<<nb_N, T>>>(N);
    k_accum_deg<<<nb_E, T>>>(ei, ew, E);
    k_dis<<<nb_N, T>>>(N);
    k_norm<<<nb_E, T>>>(ei, ew, E);

    // --- layer 1: h1_pre = x@W1, res = x@Wres ---
    gemm_tf32<<<nb_M, T>>>(x, -1, W1,   SEL_A, N, K1);
    gemm_tf32<<<nb_M, T>>>(x, -1, Wres, SEL_R, N, K1);

    // --- propagate 1 + BN/ReLU epilogue (self loop fused) ---
    k_fill0<<<nb_4, T>>>(SEL_B, n4);
    k_scatter128<<<nb_Ew, T>>>(SEL_A, SEL_B, ei, E);
    k_epilogue<<<nb_4, T>>>(SEL_B, SEL_A, b1, g1, be1, m1, v1, -1, n4);

    // --- layer 2: h2_pre = h1@W2 ---
    gemm_tf32<<<nb_M, T>>>(nullptr, SEL_B, W2, SEL_A, N, 128);

    // --- propagate 2 + residual + BN/ReLU ---
    k_fill0<<<nb_4, T>>>(SEL_B, n4);
    k_scatter128<<<nb_Ew, T>>>(SEL_A, SEL_B, ei, E);
    k_epilogue<<<nb_4, T>>>(SEL_B, SEL_A, b2, g2, be2, m2, v2, SEL_R, n4);

    // --- layer 3: scalar conv ---
    k_gemv_s<<<nb_warp, T>>>(SEL_B, W3, N);
    k_out_init<<<nb_N, T>>>(b3, out, N);
    k_scatter_s<<<nb_E, T>>>(ei, out, E);
}

// round 6
// speedup vs baseline: 1.7175x; 1.2655x over previous
#include <cuda_runtime.h>
#include <mma.h>
#include <math.h>

using namespace nvcuda;

#define NN 100000
#define EE 1600000
#define HH 128
#define NPAD (NN + 128)
#define SCAN_B 512
#define SCAN_NB ((NN + SCAN_B - 1) / SCAN_B)   // 196

// ---------------- scratch ----------------------------------------------------
__device__ float4 g_bufA4[(size_t)NPAD * HH / 4];
__device__ float4 g_bufB4[(size_t)NPAD * HH / 4];
__device__ float4 g_res4 [(size_t)NPAD * HH / 4];
__device__ float  g_dis [NN];
__device__ float  g_deg [NN];
__device__ float  g_s   [NN];
__device__ int    g_cnt [NN];
__device__ int    g_cur [NN];
__device__ int    g_partial[NN];
__device__ int    g_bsum[SCAN_B];
__device__ int    g_rowptr[NN + 1];
__device__ int    g_srcs[EE];
__device__ float  g_wS [EE];

#define SEL_A 0
#define SEL_B 1
#define SEL_R 2
__device__ __forceinline__ float* pick(int sel) {
    return sel == SEL_A ? (float*)g_bufA4
         : (sel == SEL_B ? (float*)g_bufB4 : (float*)g_res4);
}

// ---------------- CSR build --------------------------------------------------
__global__ void k_init(int n) {
    int i = blockIdx.x * blockDim.x + threadIdx.x;
    if (i < n) { g_deg[i] = 1.0f; g_cnt[i] = 0; g_cur[i] = 0; }
}

__global__ void k_edge_count(const int* __restrict__ ei,
                             const float* __restrict__ ew, int E) {
    int e = blockIdx.x * blockDim.x + threadIdx.x;
    if (e < E) {
        int c = ei[E + e];
        atomicAdd(&g_deg[c], ew[e]);
        atomicAdd(&g_cnt[c], 1);
    }
}

__global__ void k_dis(int n) {
    int i = blockIdx.x * blockDim.x + threadIdx.x;
    if (i < n) g_dis[i] = rsqrtf(g_deg[i]);
}

__global__ void k_scan1(int n) {           // grid = SCAN_NB, block = SCAN_B
    __shared__ int sh[SCAN_B];
    int i = blockIdx.x * SCAN_B + threadIdx.x;
    int v = (i < n) ? g_cnt[i] : 0;
    sh[threadIdx.x] = v;
    __syncthreads();
    for (int o = 1; o < SCAN_B; o <<= 1) {
        int t = (threadIdx.x >= o) ? sh[threadIdx.x - o] : 0;
        __syncthreads();
        sh[threadIdx.x] += t;
        __syncthreads();
    }
    if (i < n) g_partial[i] = sh[threadIdx.x] - v;          // exclusive
    if (threadIdx.x == SCAN_B - 1) g_bsum[blockIdx.x] = sh[threadIdx.x];
}

__global__ void k_scan2(int nb) {          // 1 block of SCAN_B
    __shared__ int sh[SCAN_B];
    int v = (threadIdx.x < nb) ? g_bsum[threadIdx.x] : 0;
    sh[threadIdx.x] = v;
    __syncthreads();
    for (int o = 1; o < SCAN_B; o <<= 1) {
        int t = (threadIdx.x >= o) ? sh[threadIdx.x - o] : 0;
        __syncthreads();
        sh[threadIdx.x] += t;
        __syncthreads();
    }
    if (threadIdx.x < nb) g_bsum[threadIdx.x] = sh[threadIdx.x] - v;  // exclusive
}

__global__ void k_scan3(int n, int E) {
    int i = blockIdx.x * blockDim.x + threadIdx.x;
    if (i < n) g_rowptr[i] = g_partial[i] + g_bsum[i / SCAN_B];
    if (i == 0) g_rowptr[n] = E;
}

__global__ void k_fillcsr(const int* __restrict__ ei,
                          const float* __restrict__ ew, int E) {
    int e = blockIdx.x * blockDim.x + threadIdx.x;
    if (e < E) {
        int r = ei[e];
        int c = ei[E + e];
        int pos = g_rowptr[c] + atomicAdd(&g_cur[c], 1);
        g_srcs[pos] = r;
        g_wS[pos]   = g_dis[r] * ew[e] * g_dis[c];
    }
}

// ---------------- tf32 tensor-core GEMM: C[M,128] = A[M,K] @ B[K,128] --------
__global__ __launch_bounds__(256)
void gemm_tf32(const float* __restrict__ A_ext, int selA,
               const float* __restrict__ B, int selC, int M, int K) {
    const float* A = (selA < 0) ? A_ext : pick(selA);
    float* C = pick(selC);

    __shared__ float As[128][40];
    __shared__ float Bs[32][136];

    int tid = threadIdx.x;
    int wid = tid >> 5;
    int warpM = wid >> 2;
    int warpN = wid & 3;
    int row0 = blockIdx.x * 128;

    wmma::fragment<wmma::accumulator, 16, 16, 8, float> acc[4][2];
    #pragma unroll
    for (int i = 0; i < 4; i++)
        #pragma unroll
        for (int j = 0; j < 2; j++) wmma::fill_fragment(acc[i][j], 0.0f);

    int ar = tid >> 3;
    int ac = (tid & 7) * 4;
    int br = tid >> 6;
    int bc = (tid & 63) * 2;

    for (int k0 = 0; k0 < K; k0 += 32) {
        #pragma unroll
        for (int p = 0; p < 4; p++) {
            int r = ar + p * 32;
            int gr = row0 + r;
            float4 v = make_float4(0.f, 0.f, 0.f, 0.f);
            if (gr < M) v = *(const float4*)(A + (size_t)gr * K + k0 + ac);
            *(float4*)&As[r][ac] = v;
        }
        #pragma unroll
        for (int p = 0; p < 8; p++) {
            int r = br + p * 4;
            float2 v = *(const float2*)(B + (size_t)(k0 + r) * 128 + bc);
            *(float2*)&Bs[r][bc] = v;
        }
        __syncthreads();

        #pragma unroll
        for (int kk = 0; kk < 32; kk += 8) {
            wmma::fragment<wmma::matrix_a, 16, 16, 8, wmma::precision::tf32, wmma::row_major> ah[4], al[4];
            wmma::fragment<wmma::matrix_b, 16, 16, 8, wmma::precision::tf32, wmma::row_major> bh[2], bl[2];
            #pragma unroll
            for (int i = 0; i < 4; i++) {
                wmma::load_matrix_sync(ah[i], &As[warpM * 64 + i * 16][kk], 40);
                #pragma unroll
                for (int t = 0; t < ah[i].num_elements; t++) {
                    float x = ah[i].x[t];
                    float h = wmma::__float_to_tf32(x);
                    ah[i].x[t] = h;
                    al[i].x[t] = wmma::__float_to_tf32(x - h);
                }
            }
            #pragma unroll
            for (int j = 0; j < 2; j++) {
                wmma::load_matrix_sync(bh[j], &Bs[kk][warpN * 32 + j * 16], 136);
                #pragma unroll
                for (int t = 0; t < bh[j].num_elements; t++) {
                    float x = bh[j].x[t];
                    float h = wmma::__float_to_tf32(x);
                    bh[j].x[t] = h;
                    bl[j].x[t] = wmma::__float_to_tf32(x - h);
                }
            }
            #pragma unroll
            for (int i = 0; i < 4; i++)
                #pragma unroll
                for (int j = 0; j < 2; j++) {
                    wmma::mma_sync(acc[i][j], al[i], bh[j], acc[i][j]);
                    wmma::mma_sync(acc[i][j], ah[i], bl[j], acc[i][j]);
                    wmma::mma_sync(acc[i][j], ah[i], bh[j], acc[i][j]);
                }
        }
        __syncthreads();
    }

    #pragma unroll
    for (int i = 0; i < 4; i++)
        #pragma unroll
        for (int j = 0; j < 2; j++) {
            float* cp = C + (size_t)(row0 + warpM * 64 + i * 16) * 128 + warpN * 32 + j * 16;
            wmma::store_matrix_sync(cp, acc[i][j], 128, wmma::mem_row_major);
        }
}

// ---------------- fused CSR gather + selfloop + bias (+res) + BN + ReLU ------
// One warp per destination node; lane owns a float4 of the 128-wide row.
// Optionally also computes s[node] = out_row . w3 (fused GEMV).
__global__ __launch_bounds__(256)
void k_gather_ep(int selH, int selOut,
                 const float* __restrict__ bvec,
                 const float* __restrict__ g, const float* __restrict__ be,
                 const float* __restrict__ m, const float* __restrict__ v,
                 int selRes, const float* __restrict__ w3, int n) {
    int warp = (blockIdx.x * blockDim.x + threadIdx.x) >> 5;
    if (warp >= n) return;
    int lane = threadIdx.x & 31;
    const float* h = pick(selH);

    float d = g_dis[warp];
    float d2 = d * d;
    float4 p = *(const float4*)(h + (size_t)warp * 128 + lane * 4);
    float4 a;
    a.x = p.x * d2; a.y = p.y * d2; a.z = p.z * d2; a.w = p.w * d2;

    int beg = g_rowptr[warp], end = g_rowptr[warp + 1];
    int k = beg;
    for (; k + 1 < end; k += 2) {
        int   r0 = g_srcs[k],   r1 = g_srcs[k + 1];
        float w0 = g_wS[k],     w1 = g_wS[k + 1];
        float4 h0 = *(const float4*)(h + (size_t)r0 * 128 + lane * 4);
        float4 h1 = *(const float4*)(h + (size_t)r1 * 128 + lane * 4);
        a.x += h0.x * w0 + h1.x * w1;
        a.y += h0.y * w0 + h1.y * w1;
        a.z += h0.z * w0 + h1.z * w1;
        a.w += h0.w * w0 + h1.w * w1;
    }
    if (k < end) {
        int   r0 = g_srcs[k];
        float w0 = g_wS[k];
        float4 h0 = *(const float4*)(h + (size_t)r0 * 128 + lane * 4);
        a.x += h0.x * w0; a.y += h0.y * w0; a.z += h0.z * w0; a.w += h0.w * w0;
    }

    int j4 = lane * 4;
    float4 bv = *(const float4*)(bvec + j4);
    a.x += bv.x; a.y += bv.y; a.z += bv.z; a.w += bv.w;
    if (selRes >= 0) {
        float4 rr = *(const float4*)(pick(selRes) + (size_t)warp * 128 + j4);
        a.x += rr.x; a.y += rr.y; a.z += rr.z; a.w += rr.w;
    }
    float4 gv = *(const float4*)(g + j4);
    float4 vv = *(const float4*)(v + j4);
    float4 mv = *(const float4*)(m + j4);
    float4 bb = *(const float4*)(be + j4);
    float4 o;
    o.x = fmaxf((a.x - mv.x) * (gv.x * rsqrtf(vv.x + 1e-5f)) + bb.x, 0.f);
    o.y = fmaxf((a.y - mv.y) * (gv.y * rsqrtf(vv.y + 1e-5f)) + bb.y, 0.f);
    o.z = fmaxf((a.z - mv.z) * (gv.z * rsqrtf(vv.z + 1e-5f)) + bb.z, 0.f);
    o.w = fmaxf((a.w - mv.w) * (gv.w * rsqrtf(vv.w + 1e-5f)) + bb.w, 0.f);
    *(float4*)(pick(selOut) + (size_t)warp * 128 + j4) = o;

    if (w3) {   // fused GEMV: s = o . w3
        float4 wv = ((const float4*)w3)[lane];
        float s = o.x * wv.x + o.y * wv.y + o.z * wv.z + o.w * wv.w;
        #pragma unroll
        for (int off = 16; off > 0; off >>= 1) s += __shfl_down_sync(0xffffffffu, s, off);
        if (lane == 0) g_s[warp] = s;
    }
}

// ---------------- layer 3: scalar CSR gather --------------------------------
__global__ void k_out(const float* __restrict__ b3, float* __restrict__ out, int n) {
    int i = blockIdx.x * blockDim.x + threadIdx.x;
    if (i >= n) return;
    float d = g_dis[i];
    float acc = b3[0] + g_s[i] * d * d;
    int end = g_rowptr[i + 1];
    for (int k = g_rowptr[i]; k < end; k++)
        acc += g_s[g_srcs[k]] * g_wS[k];
    out[i] = acc;
}

// ---------------- launch ----------------------------------------------------
extern "C" void kernel_launch(void* const* d_in, const int* in_sizes, int n_in,
                              void* d_out, int out_size) {
    const float* x    = (const float*)d_in[0];
    const int*   ei   = (const int*)d_in[1];     // int32 (JAX x64 disabled)
    const float* ew   = (const float*)d_in[2];
    const float* W1   = (const float*)d_in[3];
    const float* b1   = (const float*)d_in[4];
    const float* W2   = (const float*)d_in[5];
    const float* b2   = (const float*)d_in[6];
    const float* W3   = (const float*)d_in[7];
    const float* b3   = (const float*)d_in[8];
    const float* Wres = (const float*)d_in[9];
    const float* g1   = (const float*)d_in[10];
    const float* be1  = (const float*)d_in[11];
    const float* m1   = (const float*)d_in[12];
    const float* v1   = (const float*)d_in[13];
    const float* g2   = (const float*)d_in[14];
    const float* be2  = (const float*)d_in[15];
    const float* m2   = (const float*)d_in[16];
    const float* v2   = (const float*)d_in[17];
    float* out = (float*)d_out;
    (void)n_in;

    const int N  = out_size;          // 100000
    const int E  = in_sizes[1] / 2;   // 1600000
    const int K1 = in_sizes[0] / N;   // 256

    const int T = 256;
    int nb_N    = (N + T - 1) / T;
    int nb_E    = (E + T - 1) / T;
    int nb_M    = (N + 127) / 128;
    int nb_warp = (N * 32 + T - 1) / T;

    // --- CSR build + normalization ---
    k_init<<<nb_N, T>>>(N);
    k_edge_count<<<nb_E, T>>>(ei, ew, E);
    k_dis<<<nb_N, T>>>(N);
    k_scan1<<<SCAN_NB, SCAN_B>>>(N);
    k_scan2<<<1, SCAN_B>>>(SCAN_NB);
    k_scan3<<<nb_N, T>>>(N, E);
    k_fillcsr<<<nb_E, T>>>(ei, ew, E);

    // --- layer 1: h1_pre = x@W1, res = x@Wres ---
    gemm_tf32<<<nb_M, T>>>(x, -1, W1,   SEL_A, N, K1);
    gemm_tf32<<<nb_M, T>>>(x, -1, Wres, SEL_R, N, K1);

    // --- propagate 1 (gather, fused epilogue) ---
    k_gather_ep<<<nb_warp, T>>>(SEL_A, SEL_B, b1, g1, be1, m1, v1, -1, nullptr, N);

    // --- layer 2: h2_pre = h1@W2 ---
    gemm_tf32<<<nb_M, T>>>(nullptr, SEL_B, W2, SEL_A, N, 128);

    // --- propagate 2 (gather, fused epilogue + residual + GEMV w3) ---
    k_gather_ep<<<nb_warp, T>>>(SEL_A, SEL_B, b2, g2, be2, m2, v2, SEL_R, W3, N);

    // --- layer 3: scalar gather ---
    k_out<<<nb_N, T>>>(b3, out, N);
}

// round 7
// speedup vs baseline: 2.8236x; 1.6440x over previous
#include <cuda_runtime.h>
#include <cuda_bf16.h>
#include <mma.h>
#include <math.h>

using namespace nvcuda;

#define NN 100000
#define EE 1600000
#define HH 128
#define NPAD (NN + 128)
#define SCAN_B 512
#define SCAN_NB ((NN + SCAN_B - 1) / SCAN_B)   // 196

// ---------------- scratch ----------------------------------------------------
__device__ float4 g_bufA4[(size_t)NPAD * HH / 4];
__device__ float4 g_bufB4[(size_t)NPAD * HH / 4];
__device__ float4 g_res4 [(size_t)NPAD * HH / 4];
__device__ float  g_dis [NN];
__device__ float  g_deg [NN];
__device__ float  g_s   [NN];
__device__ int    g_cnt [NN];
__device__ int    g_cur [NN];
__device__ int    g_partial[NN];
__device__ int    g_bsum[SCAN_B];
__device__ int    g_rowptr[NN + 1];
__device__ int    g_srcs[EE];
__device__ float  g_wS [EE];

#define SEL_A 0
#define SEL_B 1
#define SEL_R 2
__device__ __forceinline__ float* pick(int sel) {
    return sel == SEL_A ? (float*)g_bufA4
         : (sel == SEL_B ? (float*)g_bufB4 : (float*)g_res4);
}

// ---------------- CSR build --------------------------------------------------
__global__ void k_init(int n) {
    int i = blockIdx.x * blockDim.x + threadIdx.x;
    if (i < n) { g_deg[i] = 1.0f; g_cnt[i] = 0; g_cur[i] = 0; }
}

__global__ void k_edge_count(const int* __restrict__ ei,
                             const float* __restrict__ ew, int E) {
    int e = blockIdx.x * blockDim.x + threadIdx.x;
    if (e < E) {
        int c = ei[E + e];
        atomicAdd(&g_deg[c], ew[e]);
        atomicAdd(&g_cnt[c], 1);
    }
}

__global__ void k_dis(int n) {
    int i = blockIdx.x * blockDim.x + threadIdx.x;
    if (i < n) g_dis[i] = rsqrtf(g_deg[i]);
}

__global__ void k_scan1(int n) {           // grid = SCAN_NB, block = SCAN_B
    __shared__ int sh[SCAN_B];
    int i = blockIdx.x * SCAN_B + threadIdx.x;
    int v = (i < n) ? g_cnt[i] : 0;
    sh[threadIdx.x] = v;
    __syncthreads();
    for (int o = 1; o < SCAN_B; o <<= 1) {
        int t = (threadIdx.x >= o) ? sh[threadIdx.x - o] : 0;
        __syncthreads();
        sh[threadIdx.x] += t;
        __syncthreads();
    }
    if (i < n) g_partial[i] = sh[threadIdx.x] - v;          // exclusive
    if (threadIdx.x == SCAN_B - 1) g_bsum[blockIdx.x] = sh[threadIdx.x];
}

__global__ void k_scan2(int nb) {          // 1 block of SCAN_B
    __shared__ int sh[SCAN_B];
    int v = (threadIdx.x < nb) ? g_bsum[threadIdx.x] : 0;
    sh[threadIdx.x] = v;
    __syncthreads();
    for (int o = 1; o < SCAN_B; o <<= 1) {
        int t = (threadIdx.x >= o) ? sh[threadIdx.x - o] : 0;
        __syncthreads();
        sh[threadIdx.x] += t;
        __syncthreads();
    }
    if (threadIdx.x < nb) g_bsum[threadIdx.x] = sh[threadIdx.x] - v;  // exclusive
}

__global__ void k_scan3(int n, int E) {
    int i = blockIdx.x * blockDim.x + threadIdx.x;
    if (i < n) g_rowptr[i] = g_partial[i] + g_bsum[i / SCAN_B];
    if (i == 0) g_rowptr[n] = E;
}

__global__ void k_fillcsr(const int* __restrict__ ei,
                          const float* __restrict__ ew, int E) {
    int e = blockIdx.x * blockDim.x + threadIdx.x;
    if (e < E) {
        int r = ei[e];
        int c = ei[E + e];
        int pos = g_rowptr[c] + atomicAdd(&g_cur[c], 1);
        g_srcs[pos] = r;
        g_wS[pos]   = g_dis[r] * ew[e] * g_dis[c];
    }
}

// ---------------- bf16x3 tensor-core GEMM: C[M,128] = A[M,K] @ B[K,128] ------
// Block tile 128x128, BK=32, 256 threads (8 warps: 2x4), warp tile 64x32.
// fp32 -> bf16 hi/lo split hoisted into the smem store; per k-step issue
// 3 bf16 MMAs: ah*bh + al*bh + ah*bl (al*bl term ~2^-18, dropped).
#define ASTR 40
#define BSTR 136
__global__ __launch_bounds__(256)
void gemm_bf16x3(const float* __restrict__ A_ext, int selA,
                 const float* __restrict__ B, int selC, int M, int K) {
    const float* A = (selA < 0) ? A_ext : pick(selA);
    float* C = pick(selC);

    __shared__ __nv_bfloat16 AsH[128][ASTR], AsL[128][ASTR];
    __shared__ __nv_bfloat16 BsH[32][BSTR],  BsL[32][BSTR];

    int tid = threadIdx.x;
    int wid = tid >> 5;
    int warpM = wid >> 2;     // 0..1 -> 64 rows
    int warpN = wid & 3;      // 0..3 -> 32 cols
    int row0 = blockIdx.x * 128;

    wmma::fragment<wmma::accumulator, 16, 16, 16, float> acc[4][2];
    #pragma unroll
    for (int i = 0; i < 4; i++)
        #pragma unroll
        for (int j = 0; j < 2; j++) wmma::fill_fragment(acc[i][j], 0.0f);

    int ar = tid >> 3;            // 0..31
    int ac = (tid & 7) * 4;       // 0..28
    int br = tid >> 6;            // 0..3
    int bc = (tid & 63) * 2;      // 0..126

    for (int k0 = 0; k0 < K; k0 += 32) {
        // A tile: 128x32 fp32 -> bf16 hi/lo
        #pragma unroll
        for (int p = 0; p < 4; p++) {
            int r = ar + p * 32;
            int gr = row0 + r;
            float4 v = make_float4(0.f, 0.f, 0.f, 0.f);
            if (gr < M) v = *(const float4*)(A + (size_t)gr * K + k0 + ac);
            __nv_bfloat16 hx = __float2bfloat16(v.x);
            __nv_bfloat16 hy = __float2bfloat16(v.y);
            __nv_bfloat16 hz = __float2bfloat16(v.z);
            __nv_bfloat16 hw = __float2bfloat16(v.w);
            AsH[r][ac+0] = hx; AsL[r][ac+0] = __float2bfloat16(v.x - __bfloat162float(hx));
            AsH[r][ac+1] = hy; AsL[r][ac+1] = __float2bfloat16(v.y - __bfloat162float(hy));
            AsH[r][ac+2] = hz; AsL[r][ac+2] = __float2bfloat16(v.z - __bfloat162float(hz));
            AsH[r][ac+3] = hw; AsL[r][ac+3] = __float2bfloat16(v.w - __bfloat162float(hw));
        }
        // B tile: 32x128 fp32 -> bf16 hi/lo
        #pragma unroll
        for (int p = 0; p < 8; p++) {
            int r = br + p * 4;
            float2 v = *(const float2*)(B + (size_t)(k0 + r) * 128 + bc);
            __nv_bfloat16 hx = __float2bfloat16(v.x);
            __nv_bfloat16 hy = __float2bfloat16(v.y);
            BsH[r][bc+0] = hx; BsL[r][bc+0] = __float2bfloat16(v.x - __bfloat162float(hx));
            BsH[r][bc+1] = hy; BsL[r][bc+1] = __float2bfloat16(v.y - __bfloat162float(hy));
        }
        __syncthreads();

        #pragma unroll
        for (int kk = 0; kk < 32; kk += 16) {
            wmma::fragment<wmma::matrix_a, 16, 16, 16, __nv_bfloat16, wmma::row_major> ah[4], al[4];
            wmma::fragment<wmma::matrix_b, 16, 16, 16, __nv_bfloat16, wmma::row_major> bh[2], bl[2];
            #pragma unroll
            for (int i = 0; i < 4; i++) {
                wmma::load_matrix_sync(ah[i], &AsH[warpM * 64 + i * 16][kk], ASTR);
                wmma::load_matrix_sync(al[i], &AsL[warpM * 64 + i * 16][kk], ASTR);
            }
            #pragma unroll
            for (int j = 0; j < 2; j++) {
                wmma::load_matrix_sync(bh[j], &BsH[kk][warpN * 32 + j * 16], BSTR);
                wmma::load_matrix_sync(bl[j], &BsL[kk][warpN * 32 + j * 16], BSTR);
            }
            #pragma unroll
            for (int i = 0; i < 4; i++)
                #pragma unroll
                for (int j = 0; j < 2; j++) {
                    wmma::mma_sync(acc[i][j], al[i], bh[j], acc[i][j]);
                    wmma::mma_sync(acc[i][j], ah[i], bl[j], acc[i][j]);
                    wmma::mma_sync(acc[i][j], ah[i], bh[j], acc[i][j]);
                }
        }
        __syncthreads();
    }

    #pragma unroll
    for (int i = 0; i < 4; i++)
        #pragma unroll
        for (int j = 0; j < 2; j++) {
            float* cp = C + (size_t)(row0 + warpM * 64 + i * 16) * 128 + warpN * 32 + j * 16;
            wmma::store_matrix_sync(cp, acc[i][j], 128, wmma::mem_row_major);
        }
}

// ---------------- fused CSR gather + selfloop + bias (+res) + BN + ReLU ------
__global__ __launch_bounds__(256)
void k_gather_ep(int selH, int selOut,
                 const float* __restrict__ bvec,
                 const float* __restrict__ g, const float* __restrict__ be,
                 const float* __restrict__ m, const float* __restrict__ v,
                 int selRes, const float* __restrict__ w3, int n) {
    int warp = (blockIdx.x * blockDim.x + threadIdx.x) >> 5;
    if (warp >= n) return;
    int lane = threadIdx.x & 31;
    const float* h = pick(selH);

    float d = g_dis[warp];
    float d2 = d * d;
    float4 p = *(const float4*)(h + (size_t)warp * 128 + lane * 4);
    float4 a;
    a.x = p.x * d2; a.y = p.y * d2; a.z = p.z * d2; a.w = p.w * d2;

    int beg = g_rowptr[warp], end = g_rowptr[warp + 1];
    int k = beg;
    for (; k + 3 < end; k += 4) {
        int   r0 = __ldg(&g_srcs[k]),     r1 = __ldg(&g_srcs[k + 1]);
        int   r2 = __ldg(&g_srcs[k + 2]), r3 = __ldg(&g_srcs[k + 3]);
        float w0 = __ldg(&g_wS[k]),       w1 = __ldg(&g_wS[k + 1]);
        float w2 = __ldg(&g_wS[k + 2]),   w3v = __ldg(&g_wS[k + 3]);
        float4 h0 = *(const float4*)(h + (size_t)r0 * 128 + lane * 4);
        float4 h1 = *(const float4*)(h + (size_t)r1 * 128 + lane * 4);
        float4 h2 = *(const float4*)(h + (size_t)r2 * 128 + lane * 4);
        float4 h3 = *(const float4*)(h + (size_t)r3 * 128 + lane * 4);
        a.x += h0.x * w0 + h1.x * w1 + h2.x * w2 + h3.x * w3v;
        a.y += h0.y * w0 + h1.y * w1 + h2.y * w2 + h3.y * w3v;
        a.z += h0.z * w0 + h1.z * w1 + h2.z * w2 + h3.z * w3v;
        a.w += h0.w * w0 + h1.w * w1 + h2.w * w2 + h3.w * w3v;
    }
    for (; k < end; k++) {
        int   r0 = g_srcs[k];
        float w0 = g_wS[k];
        float4 h0 = *(const float4*)(h + (size_t)r0 * 128 + lane * 4);
        a.x += h0.x * w0; a.y += h0.y * w0; a.z += h0.z * w0; a.w += h0.w * w0;
    }

    int j4 = lane * 4;
    float4 bv = *(const float4*)(bvec + j4);
    a.x += bv.x; a.y += bv.y; a.z += bv.z; a.w += bv.w;
    if (selRes >= 0) {
        float4 rr = *(const float4*)(pick(selRes) + (size_t)warp * 128 + j4);
        a.x += rr.x; a.y += rr.y; a.z += rr.z; a.w += rr.w;
    }
    float4 gv = *(const float4*)(g + j4);
    float4 vv = *(const float4*)(v + j4);
    float4 mv = *(const float4*)(m + j4);
    float4 bb = *(const float4*)(be + j4);
    float4 o;
    o.x = fmaxf((a.x - mv.x) * (gv.x * rsqrtf(vv.x + 1e-5f)) + bb.x, 0.f);
    o.y = fmaxf((a.y - mv.y) * (gv.y * rsqrtf(vv.y + 1e-5f)) + bb.y, 0.f);
    o.z = fmaxf((a.z - mv.z) * (gv.z * rsqrtf(vv.z + 1e-5f)) + bb.z, 0.f);
    o.w = fmaxf((a.w - mv.w) * (gv.w * rsqrtf(vv.w + 1e-5f)) + bb.w, 0.f);
    *(float4*)(pick(selOut) + (size_t)warp * 128 + j4) = o;

    if (w3) {   // fused GEMV: s = o . w3
        float4 wv = ((const float4*)w3)[lane];
        float s = o.x * wv.x + o.y * wv.y + o.z * wv.z + o.w * wv.w;
        #pragma unroll
        for (int off = 16; off > 0; off >>= 1) s += __shfl_down_sync(0xffffffffu, s, off);
        if (lane == 0) g_s[warp] = s;
    }
}

// ---------------- layer 3: scalar CSR gather --------------------------------
__global__ void k_out(const float* __restrict__ b3, float* __restrict__ out, int n) {
    int i = blockIdx.x * blockDim.x + threadIdx.x;
    if (i >= n) return;
    float d = g_dis[i];
    float acc = b3[0] + g_s[i] * d * d;
    int end = g_rowptr[i + 1];
    for (int k = g_rowptr[i]; k < end; k++)
        acc += g_s[g_srcs[k]] * g_wS[k];
    out[i] = acc;
}

// ---------------- launch ----------------------------------------------------
extern "C" void kernel_launch(void* const* d_in, const int* in_sizes, int n_in,
                              void* d_out, int out_size) {
    const float* x    = (const float*)d_in[0];
    const int*   ei   = (const int*)d_in[1];     // int32 (JAX x64 disabled)
    const float* ew   = (const float*)d_in[2];
    const float* W1   = (const float*)d_in[3];
    const float* b1   = (const float*)d_in[4];
    const float* W2   = (const float*)d_in[5];
    const float* b2   = (const float*)d_in[6];
    const float* W3   = (const float*)d_in[7];
    const float* b3   = (const float*)d_in[8];
    const float* Wres = (const float*)d_in[9];
    const float* g1   = (const float*)d_in[10];
    const float* be1  = (const float*)d_in[11];
    const float* m1   = (const float*)d_in[12];
    const float* v1   = (const float*)d_in[13];
    const float* g2   = (const float*)d_in[14];
    const float* be2  = (const float*)d_in[15];
    const float* m2   = (const float*)d_in[16];
    const float* v2   = (const float*)d_in[17];
    float* out = (float*)d_out;
    (void)n_in;

    const int N  = out_size;          // 100000
    const int E  = in_sizes[1] / 2;   // 1600000
    const int K1 = in_sizes[0] / N;   // 256

    const int T = 256;
    int nb_N    = (N + T - 1) / T;
    int nb_E    = (E + T - 1) / T;
    int nb_M    = (N + 127) / 128;
    int nb_warp = (N * 32 + T - 1) / T;

    // --- CSR build + normalization ---
    k_init<<<nb_N, T>>>(N);
    k_edge_count<<<nb_E, T>>>(ei, ew, E);
    k_dis<<<nb_N, T>>>(N);
    k_scan1<<<SCAN_NB, SCAN_B>>>(N);
    k_scan2<<<1, SCAN_B>>>(SCAN_NB);
    k_scan3<<<nb_N, T>>>(N, E);
    k_fillcsr<<<nb_E, T>>>(ei, ew, E);

    // --- layer 1: h1_pre = x@W1, res = x@Wres ---
    gemm_bf16x3<<<nb_M, T>>>(x, -1, W1,   SEL_A, N, K1);
    gemm_bf16x3<<<nb_M, T>>>(x, -1, Wres, SEL_R, N, K1);

    // --- propagate 1 (gather, fused epilogue) ---
    k_gather_ep<<<nb_warp, T>>>(SEL_A, SEL_B, b1, g1, be1, m1, v1, -1, nullptr, N);

    // --- layer 2: h2_pre = h1@W2 ---
    gemm_bf16x3<<<nb_M, T>>>(nullptr, SEL_B, W2, SEL_A, N, 128);

    // --- propagate 2 (gather, fused epilogue + residual + GEMV w3) ---
    k_gather_ep<<<nb_warp, T>>>(SEL_A, SEL_B, b2, g2, be2, m2, v2, SEL_R, W3, N);

    // --- layer 3: scalar gather ---
    k_out<<<nb_N, T>>>(b3, out, N);
}

// round 8
// speedup vs baseline: 3.0456x; 1.0786x over previous
#include <cuda_runtime.h>
#include <cuda_bf16.h>
#include <mma.h>
#include <math.h>

using namespace nvcuda;

#define NN 100000
#define EE 1600000
#define HH 128
#define NPAD (NN + 128)
#define SCAN_B 512
#define SCAN_NB ((NN + SCAN_B - 1) / SCAN_B)   // 196

// ---------------- scratch ----------------------------------------------------
__device__ float4 g_bufA4[(size_t)NPAD * HH / 4];
__device__ float4 g_bufB4[(size_t)NPAD * HH / 4];
__device__ float4 g_res4 [(size_t)NPAD * HH / 4];
__device__ float  g_dis [NN];
__device__ float  g_deg [NN];
__device__ float  g_s   [NN];
__device__ int    g_cnt [NN];
__device__ int    g_cur [NN];
__device__ int    g_partial[NN];
__device__ int    g_bsum[SCAN_B];
__device__ int    g_rowptr[NN + 1];
__device__ int    g_srcs[EE];
__device__ float  g_wS [EE];

#define SEL_A 0
#define SEL_B 1
#define SEL_R 2
__device__ __forceinline__ float* pick(int sel) {
    return sel == SEL_A ? (float*)g_bufA4
         : (sel == SEL_B ? (float*)g_bufB4 : (float*)g_res4);
}

// ---------------- CSR build --------------------------------------------------
__global__ void k_init(int n) {
    int i = blockIdx.x * blockDim.x + threadIdx.x;
    if (i < n) { g_deg[i] = 1.0f; g_cnt[i] = 0; g_cur[i] = 0; }
}

__global__ void k_edge_count(const int* __restrict__ ei,
                             const float* __restrict__ ew, int E) {
    int e = blockIdx.x * blockDim.x + threadIdx.x;
    if (e < E) {
        int c = ei[E + e];
        atomicAdd(&g_deg[c], ew[e]);
        atomicAdd(&g_cnt[c], 1);
    }
}

__global__ void k_scan1(int n) {           // grid = SCAN_NB, block = SCAN_B
    __shared__ int sh[SCAN_B];
    int i = blockIdx.x * SCAN_B + threadIdx.x;
    int v = (i < n) ? g_cnt[i] : 0;
    sh[threadIdx.x] = v;
    __syncthreads();
    for (int o = 1; o < SCAN_B; o <<= 1) {
        int t = (threadIdx.x >= o) ? sh[threadIdx.x - o] : 0;
        __syncthreads();
        sh[threadIdx.x] += t;
        __syncthreads();
    }
    if (i < n) g_partial[i] = sh[threadIdx.x] - v;          // exclusive
    if (threadIdx.x == SCAN_B - 1) g_bsum[blockIdx.x] = sh[threadIdx.x];
}

__global__ void k_scan2(int nb) {          // 1 block of SCAN_B
    __shared__ int sh[SCAN_B];
    int v = (threadIdx.x < nb) ? g_bsum[threadIdx.x] : 0;
    sh[threadIdx.x] = v;
    __syncthreads();
    for (int o = 1; o < SCAN_B; o <<= 1) {
        int t = (threadIdx.x >= o) ? sh[threadIdx.x - o] : 0;
        __syncthreads();
        sh[threadIdx.x] += t;
        __syncthreads();
    }
    if (threadIdx.x < nb) g_bsum[threadIdx.x] = sh[threadIdx.x] - v;  // exclusive
}

__global__ void k_scan3(int n, int E) {    // rowptr assembly + dis = rsqrt(deg)
    int i = blockIdx.x * blockDim.x + threadIdx.x;
    if (i < n) {
        g_rowptr[i] = g_partial[i] + g_bsum[i / SCAN_B];
        g_dis[i] = rsqrtf(g_deg[i]);
    }
    if (i == 0) g_rowptr[n] = E;
}

__global__ void k_fillcsr(const int* __restrict__ ei,
                          const float* __restrict__ ew, int E) {
    int e = blockIdx.x * blockDim.x + threadIdx.x;
    if (e < E) {
        int r = ei[e];
        int c = ei[E + e];
        int pos = g_rowptr[c] + atomicAdd(&g_cur[c], 1);
        g_srcs[pos] = r;
        g_wS[pos]   = g_dis[r] * ew[e] * g_dis[c];
    }
}

// ---------------- bf16x3 tensor-core GEMM: C[M,128] = A[M,K] @ B[K,128] ------
// Block tile 128x128, BK=32, 256 threads (8 warps: 2x4), warp tile 64x32.
// fp32 -> bf16 hi/lo split hoisted into the smem store; per k-step 3 bf16 MMAs.
// Register prefetch of the next K-tile overlaps global latency with MMA work.
#define ASTR 40
#define BSTR 136
__global__ __launch_bounds__(256)
void gemm_bf16x3(const float* __restrict__ A_ext, int selA,
                 const float* __restrict__ B, int selC, int M, int K) {
    const float* A = (selA < 0) ? A_ext : pick(selA);
    float* C = pick(selC);

    __shared__ __nv_bfloat16 AsH[128][ASTR], AsL[128][ASTR];
    __shared__ __nv_bfloat16 BsH[32][BSTR],  BsL[32][BSTR];

    int tid = threadIdx.x;
    int wid = tid >> 5;
    int warpM = wid >> 2;     // 0..1 -> 64 rows
    int warpN = wid & 3;      // 0..3 -> 32 cols
    int row0 = blockIdx.x * 128;

    wmma::fragment<wmma::accumulator, 16, 16, 16, float> acc[4][2];
    #pragma unroll
    for (int i = 0; i < 4; i++)
        #pragma unroll
        for (int j = 0; j < 2; j++) wmma::fill_fragment(acc[i][j], 0.0f);

    int ar = tid >> 3;            // 0..31
    int ac = (tid & 7) * 4;       // 0..28
    int br = tid >> 6;            // 0..3
    int bc = (tid & 63) * 2;      // 0..126

    float4 avr[4];
    float2 bvr[8];

    // prologue: load tile k0=0 into registers
    #pragma unroll
    for (int p = 0; p < 4; p++) {
        int gr = row0 + ar + p * 32;
        avr[p] = make_float4(0.f, 0.f, 0.f, 0.f);
        if (gr < M) avr[p] = *(const float4*)(A + (size_t)gr * K + ac);
    }
    #pragma unroll
    for (int p = 0; p < 8; p++)
        bvr[p] = *(const float2*)(B + (size_t)(br + p * 4) * 128 + bc);

    int ntiles = K >> 5;
    for (int t = 0; t < ntiles; t++) {
        // convert + store current regs -> smem
        #pragma unroll
        for (int p = 0; p < 4; p++) {
            int r = ar + p * 32;
            float4 v = avr[p];
            __nv_bfloat16 hx = __float2bfloat16(v.x);
            __nv_bfloat16 hy = __float2bfloat16(v.y);
            __nv_bfloat16 hz = __float2bfloat16(v.z);
            __nv_bfloat16 hw = __float2bfloat16(v.w);
            AsH[r][ac+0] = hx; AsL[r][ac+0] = __float2bfloat16(v.x - __bfloat162float(hx));
            AsH[r][ac+1] = hy; AsL[r][ac+1] = __float2bfloat16(v.y - __bfloat162float(hy));
            AsH[r][ac+2] = hz; AsL[r][ac+2] = __float2bfloat16(v.z - __bfloat162float(hz));
            AsH[r][ac+3] = hw; AsL[r][ac+3] = __float2bfloat16(v.w - __bfloat162float(hw));
        }
        #pragma unroll
        for (int p = 0; p < 8; p++) {
            int r = br + p * 4;
            float2 v = bvr[p];
            __nv_bfloat16 hx = __float2bfloat16(v.x);
            __nv_bfloat16 hy = __float2bfloat16(v.y);
            BsH[r][bc+0] = hx; BsL[r][bc+0] = __float2bfloat16(v.x - __bfloat162float(hx));
            BsH[r][bc+1] = hy; BsL[r][bc+1] = __float2bfloat16(v.y - __bfloat162float(hy));
        }
        __syncthreads();

        // prefetch next tile (loads in flight during MMA phase)
        if (t + 1 < ntiles) {
            int k0 = (t + 1) << 5;
            #pragma unroll
            for (int p = 0; p < 4; p++) {
                int gr = row0 + ar + p * 32;
                avr[p] = make_float4(0.f, 0.f, 0.f, 0.f);
                if (gr < M) avr[p] = *(const float4*)(A + (size_t)gr * K + k0 + ac);
            }
            #pragma unroll
            for (int p = 0; p < 8; p++)
                bvr[p] = *(const float2*)(B + (size_t)(k0 + br + p * 4) * 128 + bc);
        }

        #pragma unroll
        for (int kk = 0; kk < 32; kk += 16) {
            wmma::fragment<wmma::matrix_a, 16, 16, 16, __nv_bfloat16, wmma::row_major> ah[4], al[4];
            wmma::fragment<wmma::matrix_b, 16, 16, 16, __nv_bfloat16, wmma::row_major> bh[2], bl[2];
            #pragma unroll
            for (int i = 0; i < 4; i++) {
                wmma::load_matrix_sync(ah[i], &AsH[warpM * 64 + i * 16][kk], ASTR);
                wmma::load_matrix_sync(al[i], &AsL[warpM * 64 + i * 16][kk], ASTR);
            }
            #pragma unroll
            for (int j = 0; j < 2; j++) {
                wmma::load_matrix_sync(bh[j], &BsH[kk][warpN * 32 + j * 16], BSTR);
                wmma::load_matrix_sync(bl[j], &BsL[kk][warpN * 32 + j * 16], BSTR);
            }
            #pragma unroll
            for (int i = 0; i < 4; i++)
                #pragma unroll
                for (int j = 0; j < 2; j++) {
                    wmma::mma_sync(acc[i][j], al[i], bh[j], acc[i][j]);
                    wmma::mma_sync(acc[i][j], ah[i], bl[j], acc[i][j]);
                    wmma::mma_sync(acc[i][j], ah[i], bh[j], acc[i][j]);
                }
        }
        __syncthreads();
    }

    #pragma unroll
    for (int i = 0; i < 4; i++)
        #pragma unroll
        for (int j = 0; j < 2; j++) {
            float* cp = C + (size_t)(row0 + warpM * 64 + i * 16) * 128 + warpN * 32 + j * 16;
            wmma::store_matrix_sync(cp, acc[i][j], 128, wmma::mem_row_major);
        }
}

// ---------------- fused CSR gather + selfloop + bias (+res) + BN + ReLU ------
__global__ __launch_bounds__(256)
void k_gather_ep(int selH, int selOut,
                 const float* __restrict__ bvec,
                 const float* __restrict__ g, const float* __restrict__ be,
                 const float* __restrict__ m, const float* __restrict__ v,
                 int selRes, const float* __restrict__ w3, int n) {
    int warp = (blockIdx.x * blockDim.x + threadIdx.x) >> 5;
    if (warp >= n) return;
    int lane = threadIdx.x & 31;
    const float* h = pick(selH);

    float d = g_dis[warp];
    float d2 = d * d;
    float4 p = *(const float4*)(h + (size_t)warp * 128 + lane * 4);
    float4 a;
    a.x = p.x * d2; a.y = p.y * d2; a.z = p.z * d2; a.w = p.w * d2;

    int beg = g_rowptr[warp], end = g_rowptr[warp + 1];
    int k = beg;
    for (; k + 3 < end; k += 4) {
        int   r0 = __ldg(&g_srcs[k]),     r1 = __ldg(&g_srcs[k + 1]);
        int   r2 = __ldg(&g_srcs[k + 2]), r3 = __ldg(&g_srcs[k + 3]);
        float w0 = __ldg(&g_wS[k]),       w1 = __ldg(&g_wS[k + 1]);
        float w2 = __ldg(&g_wS[k + 2]),   w3v = __ldg(&g_wS[k + 3]);
        float4 h0 = *(const float4*)(h + (size_t)r0 * 128 + lane * 4);
        float4 h1 = *(const float4*)(h + (size_t)r1 * 128 + lane * 4);
        float4 h2 = *(const float4*)(h + (size_t)r2 * 128 + lane * 4);
        float4 h3 = *(const float4*)(h + (size_t)r3 * 128 + lane * 4);
        a.x += h0.x * w0 + h1.x * w1 + h2.x * w2 + h3.x * w3v;
        a.y += h0.y * w0 + h1.y * w1 + h2.y * w2 + h3.y * w3v;
        a.z += h0.z * w0 + h1.z * w1 + h2.z * w2 + h3.z * w3v;
        a.w += h0.w * w0 + h1.w * w1 + h2.w * w2 + h3.w * w3v;
    }
    for (; k < end; k++) {
        int   r0 = g_srcs[k];
        float w0 = g_wS[k];
        float4 h0 = *(const float4*)(h + (size_t)r0 * 128 + lane * 4);
        a.x += h0.x * w0; a.y += h0.y * w0; a.z += h0.z * w0; a.w += h0.w * w0;
    }

    int j4 = lane * 4;
    float4 bv = *(const float4*)(bvec + j4);
    a.x += bv.x; a.y += bv.y; a.z += bv.z; a.w += bv.w;
    if (selRes >= 0) {
        float4 rr = *(const float4*)(pick(selRes) + (size_t)warp * 128 + j4);
        a.x += rr.x; a.y += rr.y; a.z += rr.z; a.w += rr.w;
    }
    float4 gv = *(const float4*)(g + j4);
    float4 vv = *(const float4*)(v + j4);
    float4 mv = *(const float4*)(m + j4);
    float4 bb = *(const float4*)(be + j4);
    float4 o;
    o.x = fmaxf((a.x - mv.x) * (gv.x * rsqrtf(vv.x + 1e-5f)) + bb.x, 0.f);
    o.y = fmaxf((a.y - mv.y) * (gv.y * rsqrtf(vv.y + 1e-5f)) + bb.y, 0.f);
    o.z = fmaxf((a.z - mv.z) * (gv.z * rsqrtf(vv.z + 1e-5f)) + bb.z, 0.f);
    o.w = fmaxf((a.w - mv.w) * (gv.w * rsqrtf(vv.w + 1e-5f)) + bb.w, 0.f);
    *(float4*)(pick(selOut) + (size_t)warp * 128 + j4) = o;

    if (w3) {   // fused GEMV: s = o . w3
        float4 wv = ((const float4*)w3)[lane];
        float s = o.x * wv.x + o.y * wv.y + o.z * wv.z + o.w * wv.w;
        #pragma unroll
        for (int off = 16; off > 0; off >>= 1) s += __shfl_down_sync(0xffffffffu, s, off);
        if (lane == 0) g_s[warp] = s;
    }
}

// ---------------- layer 3: scalar CSR gather --------------------------------
__global__ void k_out(const float* __restrict__ b3, float* __restrict__ out, int n) {
    int i = blockIdx.x * blockDim.x + threadIdx.x;
    if (i >= n) return;
    float d = g_dis[i];
    float acc = b3[0] + g_s[i] * d * d;
    int end = g_rowptr[i + 1];
    for (int k = g_rowptr[i]; k < end; k++)
        acc += g_s[g_srcs[k]] * g_wS[k];
    out[i] = acc;
}

// ---------------- launch ----------------------------------------------------
extern "C" void kernel_launch(void* const* d_in, const int* in_sizes, int n_in,
                              void* d_out, int out_size) {
    const float* x    = (const float*)d_in[0];
    const int*   ei   = (const int*)d_in[1];     // int32 (JAX x64 disabled)
    const float* ew   = (const float*)d_in[2];
    const float* W1   = (const float*)d_in[3];
    const float* b1   = (const float*)d_in[4];
    const float* W2   = (const float*)d_in[5];
    const float* b2   = (const float*)d_in[6];
    const float* W3   = (const float*)d_in[7];
    const float* b3   = (const float*)d_in[8];
    const float* Wres = (const float*)d_in[9];
    const float* g1   = (const float*)d_in[10];
    const float* be1  = (const float*)d_in[11];
    const float* m1   = (const float*)d_in[12];
    const float* v1   = (const float*)d_in[13];
    const float* g2   = (const float*)d_in[14];
    const float* be2  = (const float*)d_in[15];
    const float* m2   = (const float*)d_in[16];
    const float* v2   = (const float*)d_in[17];
    float* out = (float*)d_out;
    (void)n_in;

    const int N  = out_size;          // 100000
    const int E  = in_sizes[1] / 2;   // 1600000
    const int K1 = in_sizes[0] / N;   // 256

    const int T = 256;
    int nb_N    = (N + T - 1) / T;
    int nb_E    = (E + T - 1) / T;
    int nb_M    = (N + 127) / 128;
    int nb_warp = (N * 32 + T - 1) / T;

    // Side streams/events, created once on the first (non-capture) call.
    static cudaStream_t s_csr = nullptr, s_g1 = nullptr, s_gr = nullptr;
    static cudaEvent_t  e_fork = nullptr, e_csr = nullptr, e_g1 = nullptr, e_gr = nullptr;
    if (!s_csr) {
        cudaStreamCreateWithFlags(&s_csr, cudaStreamNonBlocking);
        cudaStreamCreateWithFlags(&s_g1,  cudaStreamNonBlocking);
        cudaStreamCreateWithFlags(&s_gr,  cudaStreamNonBlocking);
        cudaEventCreateWithFlags(&e_fork, cudaEventDisableTiming);
        cudaEventCreateWithFlags(&e_csr,  cudaEventDisableTiming);
        cudaEventCreateWithFlags(&e_g1,   cudaEventDisableTiming);
        cudaEventCreateWithFlags(&e_gr,   cudaEventDisableTiming);
    }

    // fork
    cudaEventRecord(e_fork, 0);
    cudaStreamWaitEvent(s_csr, e_fork, 0);
    cudaStreamWaitEvent(s_g1,  e_fork, 0);
    cudaStreamWaitEvent(s_gr,  e_fork, 0);

    // --- CSR build + normalization (stream s_csr) ---
    k_init<<<nb_N, T, 0, s_csr>>>(N);
    k_edge_count<<<nb_E, T, 0, s_csr>>>(ei, ew, E);
    k_scan1<<<SCAN_NB, SCAN_B, 0, s_csr>>>(N);
    k_scan2<<<1, SCAN_B, 0, s_csr>>>(SCAN_NB);
    k_scan3<<<nb_N, T, 0, s_csr>>>(N, E);
    k_fillcsr<<<nb_E, T, 0, s_csr>>>(ei, ew, E);
    cudaEventRecord(e_csr, s_csr);

    // --- layer 1 GEMMs (parallel streams) ---
    gemm_bf16x3<<<nb_M, T, 0, s_g1>>>(x, -1, W1,   SEL_A, N, K1);
    cudaEventRecord(e_g1, s_g1);
    gemm_bf16x3<<<nb_M, T, 0, s_gr>>>(x, -1, Wres, SEL_R, N, K1);
    cudaEventRecord(e_gr, s_gr);

    // join CSR + GEMM1 before gather1
    cudaStreamWaitEvent(0, e_csr, 0);
    cudaStreamWaitEvent(0, e_g1, 0);

    // --- propagate 1 (gather, fused epilogue) ---
    k_gather_ep<<<nb_warp, T>>>(SEL_A, SEL_B, b1, g1, be1, m1, v1, -1, nullptr, N);

    // --- layer 2: h2_pre = h1@W2 ---
    gemm_bf16x3<<<nb_M, T>>>(nullptr, SEL_B, W2, SEL_A, N, 128);

    // join GEMMres before gather2 (its only consumer)
    cudaStreamWaitEvent(0, e_gr, 0);

    // --- propagate 2 (gather, fused epilogue + residual + GEMV w3) ---
    k_gather_ep<<<nb_warp, T>>>(SEL_A, SEL_B, b2, g2, be2, m2, v2, SEL_R, W3, N);

    // --- layer 3: scalar gather ---
    k_out<<<nb_N, T>>>(b3, out, N);
}